// round 17
// baseline (speedup 1.0000x reference)
#include <cuda_runtime.h>
#include <cuda_fp16.h>
#include <cstdint>

// out[T,N] = (x[T,K] @ W[N,K]^T) * scales[N] + bias[N];  T=8192, N=4096, K=4096
//
// R16: warp-specialized producer/consumer with mbarrier decoupling.
//  - 288 threads: warps 0-7 = consumers (CTA tile 128x256, warp 64x64, fp16
//    HMMA, BK=64, fragment pipelining as R15), warp 8 = producer (all
//    cp.async fills, 4-stage ring).
//  - full[s] mbarrier (count 32): producer arrives after cp_wait confirms
//    chunk landed. empty[s] (count 8): consumer warps' lane0 arrive after
//    last read of stage s. NO block-wide __syncthreads in the main loop —
//    consumer warps never rendezvous with each other.

#define T_DIM 8192
#define N_DIM 4096
#define K_DIM 4096

#define BM 128
#define BN 256
#define BK 64
#define THREADS 288
#define KITERS (K_DIM / BK)      // 64

#define A_B 0
#define B_B 16384
#define STAGE_B 49152
#define MBAR_OFF (4 * STAGE_B)             // 196608
#define SMEM_TOTAL (MBAR_OFF + 64)         // 196672

#define SWZ(o) ((o) ^ (((o) >> 3) & 0x70))

__device__ __align__(16) __half g_x[(size_t)T_DIM * K_DIM];
__device__ __align__(16) __half g_w[(size_t)N_DIM * K_DIM];

// ---------------- asm helpers ----------------
__device__ __forceinline__ uint32_t smem_u32(const void* p) {
    uint32_t a;
    asm("{ .reg .u64 t; cvta.to.shared.u64 t, %1; cvt.u32.u64 %0, t; }" : "=r"(a) : "l"(p));
    return a;
}
__device__ __forceinline__ void cp16(uint32_t dst, const void* src) {
    asm volatile("cp.async.cg.shared.global [%0], [%1], 16;" :: "r"(dst), "l"(src));
}
__device__ __forceinline__ void cp_commit() {
    asm volatile("cp.async.commit_group;" ::: "memory");
}
__device__ __forceinline__ void cp_wait2() {
    asm volatile("cp.async.wait_group 2;" ::: "memory");
}
__device__ __forceinline__ void cp_wait1() {
    asm volatile("cp.async.wait_group 1;" ::: "memory");
}
__device__ __forceinline__ void cp_wait0() {
    asm volatile("cp.async.wait_group 0;" ::: "memory");
}
__device__ __forceinline__ void mbar_init(uint32_t a, uint32_t cnt) {
    asm volatile("mbarrier.init.shared.b64 [%0], %1;" :: "r"(a), "r"(cnt) : "memory");
}
__device__ __forceinline__ void mbar_arrive(uint32_t a) {
    asm volatile("mbarrier.arrive.shared.b64 _, [%0];" :: "r"(a) : "memory");
}
__device__ __forceinline__ void mbar_wait(uint32_t a, uint32_t parity) {
    asm volatile(
        "{\n\t.reg .pred P;\n\t"
        "LW_%=:\n\t"
        "mbarrier.try_wait.parity.acquire.cta.shared::cta.b64 P, [%0], %1, 0x989680;\n\t"
        "@P bra.uni LD_%=;\n\t"
        "bra.uni LW_%=;\n\t"
        "LD_%=:\n\t}"
        :: "r"(a), "r"(parity) : "memory");
}
__device__ __forceinline__ void ldm4(uint32_t& r0, uint32_t& r1, uint32_t& r2, uint32_t& r3,
                                     uint32_t addr) {
    asm volatile("ldmatrix.sync.aligned.m8n8.x4.shared.b16 {%0,%1,%2,%3}, [%4];"
                 : "=r"(r0), "=r"(r1), "=r"(r2), "=r"(r3) : "r"(addr));
}
__device__ __forceinline__ void mma_f16(float* d, uint32_t a0, uint32_t a1, uint32_t a2,
                                        uint32_t a3, uint32_t b0, uint32_t b1) {
    asm volatile(
        "mma.sync.aligned.m16n8k16.row.col.f32.f16.f16.f32 "
        "{%0,%1,%2,%3}, {%4,%5,%6,%7}, {%8,%9}, {%0,%1,%2,%3};"
        : "+f"(d[0]), "+f"(d[1]), "+f"(d[2]), "+f"(d[3])
        : "r"(a0), "r"(a1), "r"(a2), "r"(a3), "r"(b0), "r"(b1));
}

// ---------------- merged prepass ----------------
#define XBLKS (T_DIM * K_DIM / 8 / 256)     // 16384
#define WBLKS (N_DIM * K_DIM / 8 / 256)     // 8192

__global__ void __launch_bounds__(256)
convert_all_kernel(const float4* __restrict__ X4, const int4* __restrict__ W4)
{
    int b = blockIdx.x;
    if (b < XBLKS) {
        int i = b * 512 + threadIdx.x;
        #pragma unroll
        for (int e = 0; e < 2; e++, i += 256) {
            float4 v = X4[i];
            __half2 h0 = __floats2half2_rn(v.x, v.y);
            __half2 h1 = __floats2half2_rn(v.z, v.w);
            uint2 u;
            u.x = *reinterpret_cast<uint32_t*>(&h0);
            u.y = *reinterpret_cast<uint32_t*>(&h1);
            *reinterpret_cast<uint2*>(g_x + (size_t)i * 4) = u;
        }
    } else {
        int i = (b - XBLKS) * 512 + threadIdx.x;
        #pragma unroll
        for (int e = 0; e < 2; e++, i += 256) {
            int4 v = W4[i];
            __half2 h0 = __floats2half2_rn((float)v.x, (float)v.y);
            __half2 h1 = __floats2half2_rn((float)v.z, (float)v.w);
            uint2 u;
            u.x = *reinterpret_cast<uint32_t*>(&h0);
            u.y = *reinterpret_cast<uint32_t*>(&h1);
            *reinterpret_cast<uint2*>(g_w + (size_t)i * 4) = u;
        }
    }
}

// ---------------- main GEMM ----------------
// consumer: load one phase's B frags (4 ldm4) + A frags mt0,mt1 (2 ldm4)
__device__ __forceinline__ void load_phase01(uint32_t base, const uint32_t* aoff,
                                             const uint32_t* boff, uint32_t kp,
                                             uint32_t bf[8][2], uint32_t af[2][4]) {
    #pragma unroll
    for (int nt = 0; nt < 4; nt++) {
        uint32_t r0, r1, r2, r3;
        ldm4(r0, r1, r2, r3, base + (boff[nt] ^ kp));
        bf[nt * 2 + 0][0] = r0; bf[nt * 2 + 0][1] = r2;
        bf[nt * 2 + 1][0] = r1; bf[nt * 2 + 1][1] = r3;
    }
    #pragma unroll
    for (int mt = 0; mt < 2; mt++)
        ldm4(af[mt][0], af[mt][1], af[mt][2], af[mt][3],
             base + (aoff[mt] ^ kp));
}

__global__ void __launch_bounds__(THREADS, 1)
qlinear_hmma_kernel(const float* __restrict__ scales,
                    const float* __restrict__ bias,
                    float* __restrict__ Out)
{
    extern __shared__ char smem[];
    const uint32_t sb = smem_u32(smem);
    const int tid = threadIdx.x;
    const int wid = tid >> 5;
    const int lane = tid & 31;

    const int n0 = blockIdx.x * BN;
    const int m0 = blockIdx.y * BM;

    // mbarriers: full[s] at MBAR_OFF + s*8, empty[s] at MBAR_OFF+32 + s*8
    const uint32_t MBF = sb + MBAR_OFF;
    const uint32_t MBE = sb + MBAR_OFF + 32;

    if (tid == 0) {
        #pragma unroll
        for (int s = 0; s < 4; s++) {
            mbar_init(MBF + s * 8, 32);   // producer warp: 32 thread arrivals
            mbar_init(MBE + s * 8, 8);    // 8 consumer warps, lane0 each
        }
    }
    __syncthreads();

    if (wid == 8) {
        // ================= producer warp =================
        const int r0 = lane >> 3;           // 0..3
        const int cc = lane & 7;
        const __half* pA = g_x + (size_t)(m0 + r0) * K_DIM + cc * 8;
        const __half* pB = g_w + (size_t)(n0 + r0) * K_DIM + cc * 8;

        for (int X = 0; X < KITERS; X++) {
            const int s = X & 3;
            if (X >= 4)
                mbar_wait(MBE + s * 8, ((X - 4) >> 2) & 1);
            const uint32_t stA = sb + s * STAGE_B + A_B;
            const uint32_t stB = sb + s * STAGE_B + B_B;
            const __half* gA = pA + (size_t)X * BK;
            const __half* gB = pB + (size_t)X * BK;
            #pragma unroll 8
            for (int i = 0; i < 32; i++) {          // A: 32 segs/thread
                int row = r0 + i * 4;
                uint32_t off = ((uint32_t)row << 7) +
                               ((uint32_t)(cc ^ (row & 7)) << 4);
                cp16(stA + off, gA + (size_t)i * 4 * K_DIM);
            }
            #pragma unroll 8
            for (int i = 0; i < 64; i++) {          // B: 64 segs/thread
                int row = r0 + i * 4;
                uint32_t off = ((uint32_t)row << 7) +
                               ((uint32_t)(cc ^ (row & 7)) << 4);
                cp16(stB + off, gB + (size_t)i * 4 * K_DIM);
            }
            cp_commit();
            if (X >= 2) { cp_wait2(); mbar_arrive(MBF + ((X - 2) & 3) * 8); }
        }
        cp_wait1(); mbar_arrive(MBF + ((KITERS - 2) & 3) * 8);
        cp_wait0(); mbar_arrive(MBF + ((KITERS - 1) & 3) * 8);
        return;
    }

    // ================= consumer warps (wid 0-7) =================
    const int wm = wid & 1;        // 2 warps over M
    const int wn = wid >> 1;       // 4 warps over N

    const int frow = lane & 15;
    const int fcol = lane >> 4;
    uint32_t aoff[4], boff[4];
    #pragma unroll
    for (int mt = 0; mt < 4; mt++) {
        uint32_t row = (uint32_t)(wm * 64 + mt * 16 + frow);
        aoff[mt] = A_B + ((row << 7) ^ ((row & 7) << 4));
    }
    #pragma unroll
    for (int nt = 0; nt < 4; nt++) {
        uint32_t row = (uint32_t)(wn * 64 + nt * 16 + frow);
        boff[nt] = B_B + ((row << 7) ^ ((row & 7) << 4));
    }
    const uint32_t kbase = (uint32_t)(fcol << 4);
    const int rot = (wid >> 2) * 2;    // SMSP de-phasing (kept from R15)

    float acc[4][8][4];
    #pragma unroll
    for (int mt = 0; mt < 4; mt++)
        #pragma unroll
        for (int nf = 0; nf < 8; nf++)
            #pragma unroll
            for (int q = 0; q < 4; q++) acc[mt][nf][q] = 0.0f;

    uint32_t bf[2][8][2];
    uint32_t af01[2][2][4];

    // preload: wait chunk 0, load phase rot
    mbar_wait(MBF + 0, 0);
    load_phase01(sb, aoff, boff, kbase + (uint32_t)(rot * 32), bf[0], af01[0]);

    for (int c = 0; c < KITERS; c++) {
        const int s = c & 3;
        const uint32_t base = sb + (uint32_t)(s * STAGE_B);
        const uint32_t nbase = sb + (uint32_t)(((c + 1) & 3) * STAGE_B);

        #pragma unroll
        for (int j = 0; j < 4; j++) {
            const int cur = j & 1, nxt = cur ^ 1;
            const uint32_t kcur = kbase + (uint32_t)(((j + rot) & 3) * 32);

            // current phase's A frags mt2, mt3 (16 MMAs of cover below)
            uint32_t a2[4], a3[4];
            ldm4(a2[0], a2[1], a2[2], a2[3], base + (aoff[2] ^ kcur));
            ldm4(a3[0], a3[1], a3[2], a3[3], base + (aoff[3] ^ kcur));

            if (j < 3) {
                load_phase01(base, aoff, boff,
                             kbase + (uint32_t)((((j + 1 + rot) & 3)) * 32),
                             bf[nxt], af01[nxt]);
            } else if (c + 1 < KITERS) {
                mbar_wait(MBF + ((c + 1) & 3) * 8, ((c + 1) >> 2) & 1);
                load_phase01(nbase, aoff, boff, kbase + (uint32_t)(rot * 32),
                             bf[nxt], af01[nxt]);
            }

            #pragma unroll
            for (int nf = 0; nf < 8; nf++)
                mma_f16(acc[0][nf], af01[cur][0][0], af01[cur][0][1],
                        af01[cur][0][2], af01[cur][0][3],
                        bf[cur][nf][0], bf[cur][nf][1]);
            #pragma unroll
            for (int nf = 0; nf < 8; nf++)
                mma_f16(acc[1][nf], af01[cur][1][0], af01[cur][1][1],
                        af01[cur][1][2], af01[cur][1][3],
                        bf[cur][nf][0], bf[cur][nf][1]);
            #pragma unroll
            for (int nf = 0; nf < 8; nf++)
                mma_f16(acc[2][nf], a2[0], a2[1], a2[2], a2[3],
                        bf[cur][nf][0], bf[cur][nf][1]);
            #pragma unroll
            for (int nf = 0; nf < 8; nf++)
                mma_f16(acc[3][nf], a3[0], a3[1], a3[2], a3[3],
                        bf[cur][nf][0], bf[cur][nf][1]);

            if (j == 3 && lane == 0)
                mbar_arrive(MBE + s * 8);   // stage s fully read (after MMAs)
        }
    }

    // ---- epilogue ----
    #pragma unroll
    for (int mt = 0; mt < 4; mt++) {
        const int mrow = m0 + wm * 64 + mt * 16 + (lane >> 2);
        #pragma unroll
        for (int nf = 0; nf < 8; nf++) {
            const int n = n0 + wn * 64 + nf * 8 + (lane & 3) * 2;
            float2 sc = *reinterpret_cast<const float2*>(scales + n);
            float2 bi = *reinterpret_cast<const float2*>(bias + n);
            float2 o0, o1;
            o0.x = acc[mt][nf][0] * sc.x + bi.x;
            o0.y = acc[mt][nf][1] * sc.y + bi.y;
            o1.x = acc[mt][nf][2] * sc.x + bi.x;
            o1.y = acc[mt][nf][3] * sc.y + bi.y;
            *reinterpret_cast<float2*>(Out + (size_t)mrow * N_DIM + n) = o0;
            *reinterpret_cast<float2*>(Out + (size_t)(mrow + 8) * N_DIM + n) = o1;
        }
    }
}

// ---------------- host ----------------
extern "C" void kernel_launch(void* const* d_in, const int* in_sizes, int n_in,
                              void* d_out, int out_size)
{
    const float* x      = (const float*)d_in[0];
    const int*   w      = (const int*)d_in[1];
    const float* scales = (const float*)d_in[2];
    const float* bias   = (const float*)d_in[3];
    float* out = (float*)d_out;

    cudaFuncSetAttribute(qlinear_hmma_kernel,
                         cudaFuncAttributeMaxDynamicSharedMemorySize, SMEM_TOTAL);

    convert_all_kernel<<<XBLKS + WBLKS, 256>>>((const float4*)x, (const int4*)w);

    dim3 grid(N_DIM / BN, T_DIM / BM);   // 16 x 64
    qlinear_hmma_kernel<<<grid, THREADS, SMEM_TOTAL>>>(scales, bias, out);
}